// round 1
// baseline (speedup 1.0000x reference)
#include <cuda_runtime.h>
#include <cuda_bf16.h>

// Output depends only on per-graph means of ORIGINAL node features + tiny MLP.
// (GraphConv layers in the reference are dead code — DGL HeteroGraphConv bug,
// faithfully reproduced: port1/net1/net2 are deleted and never used.)

#define NGRAPHS 64

// Scratch: sums laid out as [b*4 + col] with col mapping {comp:0, port:1,2, net:3}
// counts as [type*64 + b] with type {comp:0, port:1, net:2}
__device__ float g_sum[NGRAPHS * 4];
__device__ float g_cnt[NGRAPHS * 3];

__global__ void zero_kernel() {
    int i = threadIdx.x;
    if (i < NGRAPHS * 4) g_sum[i] = 0.0f;
    if (i < NGRAPHS * 3) g_cnt[i] = 0.0f;
}

// Warp-cooperative segmented accumulation. gid arrays are sorted, so the
// warp-uniform fast path (shuffle reduce + 1 shared atomic per warp) covers
// virtually every iteration; boundary warps fall back to per-lane atomics.
template <int COLS>
__device__ __forceinline__ void accum_type(
    const float* __restrict__ x, const int* __restrict__ gid, int n,
    int blk0, int nblocks, float* s_sum, float* s_cnt)
{
    const int tid = threadIdx.x;
    const int stride = nblocks * blockDim.x;
    for (int base = blk0 * blockDim.x; base < n; base += stride) {
        const int i = base + tid;
        const bool valid = (i < n);
        int g = 0;
        float v[COLS];
#pragma unroll
        for (int c = 0; c < COLS; c++) v[c] = 0.0f;
        if (valid) {
            g = gid[i];
#pragma unroll
            for (int c = 0; c < COLS; c++) v[c] = x[i * COLS + c];
        }
        const unsigned vm = __ballot_sync(0xffffffffu, valid);
        const int g0 = __shfl_sync(0xffffffffu, g, 0);
        // valid lanes form a prefix, so if any lane is valid, lane 0 is.
        const bool uni = __all_sync(0xffffffffu, (!valid) || (g == g0));
        if (uni) {
            const float cnt = (float)__popc(vm);
#pragma unroll
            for (int c = 0; c < COLS; c++) {
                float s = v[c];
#pragma unroll
                for (int off = 16; off > 0; off >>= 1)
                    s += __shfl_xor_sync(0xffffffffu, s, off);
                if ((tid & 31) == 0 && vm) atomicAdd(&s_sum[g0 * COLS + c], s);
            }
            if ((tid & 31) == 0 && vm) atomicAdd(&s_cnt[g0], cnt);
        } else {
            if (valid) {
#pragma unroll
                for (int c = 0; c < COLS; c++) atomicAdd(&s_sum[g * COLS + c], v[c]);
                atomicAdd(&s_cnt[g], 1.0f);
            }
        }
    }
}

#define NB_COMP 32
#define NB_PORT 128
#define NB_NET  48
#define NB_TOTAL (NB_COMP + NB_PORT + NB_NET)

__global__ void accum_kernel(
    const float* __restrict__ h_comp, const int* __restrict__ gid_comp, int nc,
    const float* __restrict__ h_port, const int* __restrict__ gid_port, int np,
    const float* __restrict__ h_net,  const int* __restrict__ gid_net,  int nn)
{
    __shared__ float s_sum[NGRAPHS * 2];
    __shared__ float s_cnt[NGRAPHS];
    const int tid = threadIdx.x;
    if (tid < NGRAPHS * 2) s_sum[tid] = 0.0f;
    if (tid < NGRAPHS) s_cnt[tid] = 0.0f;
    __syncthreads();

    const int blk = blockIdx.x;
    int type, cols, sum_off;
    if (blk < NB_COMP) {
        accum_type<1>(h_comp, gid_comp, nc, blk, NB_COMP, s_sum, s_cnt);
        type = 0; cols = 1; sum_off = 0;
    } else if (blk < NB_COMP + NB_PORT) {
        accum_type<2>(h_port, gid_port, np, blk - NB_COMP, NB_PORT, s_sum, s_cnt);
        type = 1; cols = 2; sum_off = 1;
    } else {
        accum_type<1>(h_net, gid_net, nn, blk - NB_COMP - NB_PORT, NB_NET, s_sum, s_cnt);
        type = 2; cols = 1; sum_off = 3;
    }
    __syncthreads();

    if (tid < NGRAPHS * cols) {
        const int b = tid / cols, c = tid % cols;
        atomicAdd(&g_sum[b * 4 + sum_off + c], s_sum[tid]);
    }
    if (tid < NGRAPHS) {
        atomicAdd(&g_cnt[type * NGRAPHS + tid], s_cnt[tid]);
    }
}

// One block per graph, 128 threads (one per hidden unit).
__global__ void mlp_kernel(
    const float* __restrict__ Wc1, const float* __restrict__ bc1,
    const float* __restrict__ Wc2, const float* __restrict__ bc2,
    const float* __restrict__ Wc3, const float* __restrict__ bc3,
    float* __restrict__ out)
{
    const int b = blockIdx.x;
    const int j = threadIdx.x;  // 0..127
    __shared__ float hg[4];
    __shared__ float h1[128];
    __shared__ float h2[128];

    if (j < 4) {
        const int type = (j == 0) ? 0 : (j < 3 ? 1 : 2);
        const float c = g_cnt[type * NGRAPHS + b];
        hg[j] = g_sum[b * 4 + j] / fmaxf(c, 1.0f);
    }
    __syncthreads();

    // layer 1: [4] -> [128]
    float a = bc1[j];
#pragma unroll
    for (int k = 0; k < 4; k++) a = fmaf(hg[k], Wc1[k * 128 + j], a);
    h1[j] = fmaxf(a, 0.0f);
    __syncthreads();

    // layer 2: [128] -> [128], coalesced column reads of Wc2 (L2-resident)
    float a0 = bc2[j], a1 = 0.0f, a2 = 0.0f, a3 = 0.0f;
#pragma unroll
    for (int k = 0; k < 128; k += 4) {
        a0 = fmaf(h1[k + 0], Wc2[(k + 0) * 128 + j], a0);
        a1 = fmaf(h1[k + 1], Wc2[(k + 1) * 128 + j], a1);
        a2 = fmaf(h1[k + 2], Wc2[(k + 2) * 128 + j], a2);
        a3 = fmaf(h1[k + 3], Wc2[(k + 3) * 128 + j], a3);
    }
    h2[j] = fmaxf((a0 + a1) + (a2 + a3), 0.0f);
    __syncthreads();

    // layer 3: [128] -> [10]
    if (j < 10) {
        float c0 = bc3[j], c1 = 0.0f, c2 = 0.0f, c3 = 0.0f;
#pragma unroll
        for (int k = 0; k < 128; k += 4) {
            c0 = fmaf(h2[k + 0], Wc3[(k + 0) * 10 + j], c0);
            c1 = fmaf(h2[k + 1], Wc3[(k + 1) * 10 + j], c1);
            c2 = fmaf(h2[k + 2], Wc3[(k + 2) * 10 + j], c2);
            c3 = fmaf(h2[k + 3], Wc3[(k + 3) * 10 + j], c3);
        }
        out[b * 10 + j] = (c0 + c1) + (c2 + c3);
    }
}

extern "C" void kernel_launch(void* const* d_in, const int* in_sizes, int n_in,
                              void* d_out, int out_size)
{
    const float* h_comp   = (const float*)d_in[0];
    const float* h_port   = (const float*)d_in[1];
    const float* h_net    = (const float*)d_in[2];
    // d_in[3..6] = edge arrays: unused (dead GraphConv path)
    const int*   gid_comp = (const int*)d_in[7];
    const int*   gid_port = (const int*)d_in[8];
    const int*   gid_net  = (const int*)d_in[9];
    // d_in[10..21] = GraphConv weights/biases: unused (dead code)
    const float* Wc1 = (const float*)d_in[22];
    const float* bc1 = (const float*)d_in[23];
    const float* Wc2 = (const float*)d_in[24];
    const float* bc2 = (const float*)d_in[25];
    const float* Wc3 = (const float*)d_in[26];
    const float* bc3 = (const float*)d_in[27];

    const int nc = in_sizes[0];       // comp nodes (1 col)
    const int np = in_sizes[1] / 2;   // port nodes (2 cols)
    const int nn = in_sizes[2];       // net nodes (1 col)

    zero_kernel<<<1, 256>>>();
    accum_kernel<<<NB_TOTAL, 256>>>(h_comp, gid_comp, nc,
                                    h_port, gid_port, np,
                                    h_net,  gid_net,  nn);
    mlp_kernel<<<NGRAPHS, 128>>>(Wc1, bc1, Wc2, bc2, Wc3, bc3, (float*)d_out);
}